// round 12
// baseline (speedup 1.0000x reference)
#include <cuda_runtime.h>

// CosineSim3D factorized — L2-residency-aware, occupancy-boosted K2:
//   K1: partial sums of normalized b rows (__ldcs), resets per-batch counters
//   K2 (4 CTAs per batch, 256 thr, 6 resident/SM): score 256-row quarter,
//       exchange via g_scores + L2 counter, redundant softmax, write quarter.
//
// a, b : [128, 1024, 300] fp32   out : [128, 1024, 300] fp32

#define BATCH   128
#define NROWS   1024
#define DIM     300
#define NF4     75
#define NSUB    8
#define RSUB    (NROWS/NSUB)
#define EPSV    1e-7f

// scratch (no cudaMalloc allowed)
__device__ float4 g_part4[BATCH * NSUB * NF4];
__device__ float  g_scores[BATCH * NROWS];
__device__ int    g_done[BATCH];

__device__ __forceinline__ float dot4(float4 x, float4 y) {
    return x.x * y.x + x.y * y.y + x.z * y.z + x.w * y.w;
}
__device__ __forceinline__ void fma4(float4& a, float4 v, float s) {
    a.x += v.x * s; a.y += v.y * s; a.z += v.z * s; a.w += v.w * s;
}
__device__ __forceinline__ void add4(float4& a, float4 v) {
    a.x += v.x; a.y += v.y; a.z += v.z; a.w += v.w;
}

// ---------------------------------------------------------------------------
// K1: partial normalized-b sums (proven R4 structure + __ldcs).
// grid = 1024 (batch*8), block = 256. Also resets g_done for this replay.
// ---------------------------------------------------------------------------
__global__ __launch_bounds__(256) void partial_b_kernel(const float* __restrict__ b)
{
    const int batch = blockIdx.x >> 3;
    const int sub   = blockIdx.x & 7;
    const int warp  = threadIdx.x >> 5;
    const int lane  = threadIdx.x & 31;

    if (blockIdx.x < BATCH && threadIdx.x == 0) g_done[blockIdx.x] = 0;

    const float4 zero4 = make_float4(0.f, 0.f, 0.f, 0.f);
    const float4* b4 = reinterpret_cast<const float4*>(
        b + (size_t)batch * NROWS * DIM);

    float4 acc0 = zero4, acc1 = zero4, acc2 = zero4;

    const int r0 = sub * RSUB;
    for (int r = r0 + warp; r < r0 + RSUB; r += 8) {
        const float4* row = b4 + r * NF4;
        const float4 v0 = __ldcs(row + lane);
        const float4 v1 = __ldcs(row + lane + 32);
        const float4 v2 = (lane < NF4 - 64) ? __ldcs(row + lane + 64) : zero4;
        float ss = dot4(v0, v0) + dot4(v1, v1) + dot4(v2, v2);
#pragma unroll
        for (int o = 16; o > 0; o >>= 1)
            ss += __shfl_xor_sync(0xffffffffu, ss, o);
        const float inv = rsqrtf(fmaxf(ss, EPSV));
        fma4(acc0, v0, inv);
        fma4(acc1, v1, inv);
        fma4(acc2, v2, inv);
    }

    __shared__ float4 sw4[8][NF4 + 1];
    sw4[warp][lane]      = acc0;
    sw4[warp][lane + 32] = acc1;
    if (lane < NF4 - 64) sw4[warp][lane + 64] = acc2;
    __syncthreads();

    float4* dst = g_part4 + (batch * NSUB + sub) * NF4;
    for (int j = threadIdx.x; j < NF4; j += blockDim.x) {
        float4 t = sw4[0][j];
#pragma unroll
        for (int w = 1; w < 8; w++) add4(t, sw4[w][j]);
        dst[j] = t;
    }
}

// ---------------------------------------------------------------------------
// K2: quarter-batch score + exchange + redundant softmax + quarter write.
// grid = 512 (batch*4), block = 256 (8 warps), 6 CTAs/SM resident.
// ---------------------------------------------------------------------------
__global__ __launch_bounds__(256, 6) void score_ssw_kernel(
    const float* __restrict__ a, float* __restrict__ out)
{
    const int batch = blockIdx.x >> 2;
    const int q     = blockIdx.x & 3;
    const int warp  = threadIdx.x >> 5;
    const int lane  = threadIdx.x & 31;
    const int base  = q * 256;

    __shared__ float4 ssh4[NF4];
    __shared__ float  probs_sh[256];
    __shared__ float  red[8];
    __shared__ float  sh_M, sh_S;

    const float4 z4 = make_float4(0.f, 0.f, 0.f, 0.f);

    // fold 8 partials -> s_b (L2-resident, fixed order)
    if (threadIdx.x < NF4) {
        const float4* part = g_part4 + batch * NSUB * NF4;
        float4 t = part[threadIdx.x];
#pragma unroll
        for (int p = 1; p < NSUB; p++) add4(t, part[p * NF4 + threadIdx.x]);
        ssh4[threadIdx.x] = t;
    }
    __syncthreads();

    const float4 s0 = ssh4[lane];
    const float4 s1 = ssh4[lane + 32];
    const float4 s2 = (lane < NF4 - 64) ? ssh4[lane + 64] : z4;

    const float4* a4 = reinterpret_cast<const float4*>(a)
                     + (size_t)batch * NROWS * NF4;
    float* sc = g_scores + batch * NROWS;

    // score own quarter: 8 warps x 32 rows, warp-per-row
#pragma unroll 2
    for (int i = 0; i < 32; i++) {
        const int r = base + warp + 8 * i;
        const float4* row = a4 + r * NF4;
        const float4 v0 = __ldcs(row + lane);
        const float4 v1 = __ldcs(row + lane + 32);
        const float4 v2 = (lane < NF4 - 64) ? __ldcs(row + lane + 64) : z4;
        float dot = dot4(v0, s0) + dot4(v1, s1) + dot4(v2, s2);
        float ss  = dot4(v0, v0) + dot4(v1, v1) + dot4(v2, v2);
#pragma unroll
        for (int o = 16; o > 0; o >>= 1) {
            dot += __shfl_xor_sync(0xffffffffu, dot, o);
            ss  += __shfl_xor_sync(0xffffffffu, ss,  o);
        }
        if (lane == 0)
            sc[r] = dot * rsqrtf(fmaxf(ss, EPSV));
    }

    // exchange: publish quarter, wait for all 4 (all CTAs resident -> safe)
    __threadfence();
    __syncthreads();
    if (threadIdx.x == 0) {
        atomicAdd(&g_done[batch], 1);
        while (atomicAdd(&g_done[batch], 0) < 4) __nanosleep(100);
    }
    __syncthreads();
    __threadfence();

    // redundant softmax over 1024 scores (thread t owns rows t, t+256, t+512, t+768)
    const float x0 = __ldcg(sc + threadIdx.x);
    const float x1 = __ldcg(sc + threadIdx.x + 256);
    const float x2 = __ldcg(sc + threadIdx.x + 512);
    const float x3 = __ldcg(sc + threadIdx.x + 768);

    float m = fmaxf(fmaxf(x0, x1), fmaxf(x2, x3));
#pragma unroll
    for (int o = 16; o > 0; o >>= 1)
        m = fmaxf(m, __shfl_xor_sync(0xffffffffu, m, o));
    if (lane == 0) red[warp] = m;
    __syncthreads();
    if (warp == 0) {
        float t = (lane < 8) ? red[lane] : -3.4e38f;
#pragma unroll
        for (int o = 4; o > 0; o >>= 1)
            t = fmaxf(t, __shfl_xor_sync(0xffffffffu, t, o));
        if (lane == 0) sh_M = t;
    }
    __syncthreads();
    const float M = sh_M;

    const float e0 = __expf(x0 - M);
    const float e1 = __expf(x1 - M);
    const float e2 = __expf(x2 - M);
    const float e3 = __expf(x3 - M);
    float sum = e0 + e1 + e2 + e3;
#pragma unroll
    for (int o = 16; o > 0; o >>= 1)
        sum += __shfl_xor_sync(0xffffffffu, sum, o);
    if (lane == 0) red[warp] = sum;
    __syncthreads();
    if (warp == 0) {
        float t = (lane < 8) ? red[lane] : 0.f;
#pragma unroll
        for (int o = 4; o > 0; o >>= 1)
            t += __shfl_xor_sync(0xffffffffu, t, o);
        if (lane == 0) sh_S = t;
    }
    __syncthreads();
    const float inv = __frcp_rn(sh_S);

    // own quarter's prob: row base+tid is this thread's element #q
    const float eq = (q == 0) ? e0 : (q == 1) ? e1 : (q == 2) ? e2 : e3;
    probs_sh[threadIdx.x] = eq * inv;
    __syncthreads();

    // write own quarter: 8 warps x 32 rows, plain write-back stores
    float4* o4 = reinterpret_cast<float4*>(out)
               + ((size_t)batch * NROWS + base) * NF4;
#pragma unroll 4
    for (int i = 0; i < 32; i++) {
        const int r = warp + 8 * i;
        const float p = probs_sh[r];
        const float4 pv = make_float4(p, p, p, p);
        float4* row = o4 + r * NF4;
        row[lane]      = pv;
        row[lane + 32] = pv;
        if (lane < NF4 - 64) row[lane + 64] = pv;
    }
}

// ---------------------------------------------------------------------------
extern "C" void kernel_launch(void* const* d_in, const int* in_sizes, int n_in,
                              void* d_out, int out_size)
{
    const float* a = (const float*)d_in[0];
    const float* b = (const float*)d_in[1];
    float* out = (float*)d_out;

    partial_b_kernel<<<BATCH * NSUB, 256>>>(b);
    score_ssw_kernel<<<BATCH * 4, 256>>>(a, out);
}

// round 14
// speedup vs baseline: 1.1680x; 1.1680x over previous
#include <cuda_runtime.h>

// CosineSim3D — single fully-fused kernel (per batch):
//   phase B: s_b = sum of normalized b rows   (ldcs, float4, warp-per-row)
//   phase A: score a rows vs s_b              (ldcs, 2-row interleave)
//   softmax over 1024 scores
//   broadcast write out (plain write-back stores -> L2-resident)
//
// a, b : [128, 1024, 300] fp32   out : [128, 1024, 300] fp32

#define BATCH   128
#define NROWS   1024
#define DIM     300
#define NF4     75
#define EPSV    1e-7f

__device__ __forceinline__ float dot4(float4 x, float4 y) {
    return x.x * y.x + x.y * y.y + x.z * y.z + x.w * y.w;
}
__device__ __forceinline__ void fma4(float4& a, float4 v, float s) {
    a.x += v.x * s; a.y += v.y * s; a.z += v.z * s; a.w += v.w * s;
}
__device__ __forceinline__ void add4(float4& a, float4 v) {
    a.x += v.x; a.y += v.y; a.z += v.z; a.w += v.w;
}

// ---------------------------------------------------------------------------
// grid = 128 (batch), block = 1024 (32 warps)
// ---------------------------------------------------------------------------
__global__ __launch_bounds__(1024, 1) void fused_all_kernel(
    const float* __restrict__ a, const float* __restrict__ b,
    float* __restrict__ out)
{
    const int batch = blockIdx.x;
    const int warp  = threadIdx.x >> 5;
    const int lane  = threadIdx.x & 31;

    __shared__ float4 sw4[32][NF4 + 1];   // 38.9 KB cross-warp partials
    __shared__ float4 ssh4[NF4];          // s_b
    __shared__ float  probs[NROWS];
    __shared__ float  red[32];

    const float4 z4 = make_float4(0.f, 0.f, 0.f, 0.f);

    // ---- phase B: s_b = sum of normalized b rows -------------------------
    {
        const float4* b4 = reinterpret_cast<const float4*>(b)
                         + (size_t)batch * NROWS * NF4;
        float4 acc0 = z4, acc1 = z4, acc2 = z4;

        for (int r = warp; r < NROWS; r += 32) {
            const float4* row = b4 + r * NF4;
            const float4 v0 = __ldcs(row + lane);
            const float4 v1 = __ldcs(row + lane + 32);
            const float4 v2 = (lane < NF4 - 64) ? __ldcs(row + lane + 64) : z4;
            float ss = dot4(v0, v0) + dot4(v1, v1) + dot4(v2, v2);
#pragma unroll
            for (int o = 16; o > 0; o >>= 1)
                ss += __shfl_xor_sync(0xffffffffu, ss, o);
            const float inv = rsqrtf(fmaxf(ss, EPSV));
            fma4(acc0, v0, inv);
            fma4(acc1, v1, inv);
            fma4(acc2, v2, inv);
        }
        sw4[warp][lane]      = acc0;
        sw4[warp][lane + 32] = acc1;
        if (lane < NF4 - 64) sw4[warp][lane + 64] = acc2;
    }
    __syncthreads();

    // fold 32 warp-partials -> ssh4 (75 active threads, fixed order)
    if (threadIdx.x < NF4) {
        float4 t = sw4[0][threadIdx.x];
#pragma unroll
        for (int w = 1; w < 32; w++) add4(t, sw4[w][threadIdx.x]);
        ssh4[threadIdx.x] = t;
    }
    __syncthreads();

    // ---- phase A: scores of a rows (2-row interleave) --------------------
    {
        const float4 s0 = ssh4[lane];
        const float4 s1 = ssh4[lane + 32];
        const float4 s2 = (lane < NF4 - 64) ? ssh4[lane + 64] : z4;

        const float4* a4 = reinterpret_cast<const float4*>(a)
                         + (size_t)batch * NROWS * NF4;

#pragma unroll 2
        for (int i = 0; i < 16; i++) {
            const int rA = warp + 64 * i;
            const float4* rowA = a4 + rA * NF4;
            const float4* rowB = rowA + 32 * NF4;
            const float4 A0 = __ldcs(rowA + lane);
            const float4 A1 = __ldcs(rowA + lane + 32);
            const float4 B0 = __ldcs(rowB + lane);
            const float4 B1 = __ldcs(rowB + lane + 32);
            const float4 A2 = (lane < NF4 - 64) ? __ldcs(rowA + lane + 64) : z4;
            const float4 B2 = (lane < NF4 - 64) ? __ldcs(rowB + lane + 64) : z4;

            float dA = dot4(A0, s0) + dot4(A1, s1) + dot4(A2, s2);
            float nA = dot4(A0, A0) + dot4(A1, A1) + dot4(A2, A2);
            float dB = dot4(B0, s0) + dot4(B1, s1) + dot4(B2, s2);
            float nB = dot4(B0, B0) + dot4(B1, B1) + dot4(B2, B2);
#pragma unroll
            for (int o = 16; o > 0; o >>= 1) {
                dA += __shfl_xor_sync(0xffffffffu, dA, o);
                nA += __shfl_xor_sync(0xffffffffu, nA, o);
                dB += __shfl_xor_sync(0xffffffffu, dB, o);
                nB += __shfl_xor_sync(0xffffffffu, nB, o);
            }
            if (lane == 0) {
                probs[rA]      = dA * rsqrtf(fmaxf(nA, EPSV));
                probs[rA + 32] = dB * rsqrtf(fmaxf(nB, EPSV));
            }
        }
    }
    __syncthreads();

    // ---- softmax over 1024 scores (thread t owns element t) --------------
    const float x = probs[threadIdx.x];

    float m = x;
#pragma unroll
    for (int o = 16; o > 0; o >>= 1)
        m = fmaxf(m, __shfl_xor_sync(0xffffffffu, m, o));
    if (lane == 0) red[warp] = m;
    __syncthreads();
    if (warp == 0) {
        float t = red[lane];
#pragma unroll
        for (int o = 16; o > 0; o >>= 1)
            t = fmaxf(t, __shfl_xor_sync(0xffffffffu, t, o));
        if (lane == 0) red[0] = t;
    }
    __syncthreads();
    const float M = red[0];

    const float e = __expf(x - M);

    float sum = e;
#pragma unroll
    for (int o = 16; o > 0; o >>= 1)
        sum += __shfl_xor_sync(0xffffffffu, sum, o);
    __syncthreads();                  // red[] reuse barrier
    if (lane == 0) red[warp] = sum;
    __syncthreads();
    if (warp == 0) {
        float t = red[lane];
#pragma unroll
        for (int o = 16; o > 0; o >>= 1)
            t += __shfl_xor_sync(0xffffffffu, t, o);
        if (lane == 0) red[0] = t;
    }
    __syncthreads();

    probs[threadIdx.x] = e * __frcp_rn(red[0]);
    __syncthreads();

    // ---- broadcast write: warp-per-row, plain write-back stores ----------
    float4* o4 = reinterpret_cast<float4*>(out) + (size_t)batch * NROWS * NF4;
#pragma unroll 4
    for (int r = warp; r < NROWS; r += 32) {
        const float p = probs[r];
        const float4 pv = make_float4(p, p, p, p);
        float4* row = o4 + r * NF4;
        row[lane]      = pv;
        row[lane + 32] = pv;
        if (lane < NF4 - 64) row[lane + 64] = pv;
    }
}

// ---------------------------------------------------------------------------
extern "C" void kernel_launch(void* const* d_in, const int* in_sizes, int n_in,
                              void* d_out, int out_size)
{
    const float* a = (const float*)d_in[0];
    const float* b = (const float*)d_in[1];
    float* out = (float*)d_out;

    fused_all_kernel<<<BATCH, 1024>>>(a, b, out);
}

// round 15
// speedup vs baseline: 1.1734x; 1.0047x over previous
#include <cuda_runtime.h>

// CosineSim3D — single fully-fused kernel (per batch):
//   phase B: s_b = sum of normalized b rows   (ldcs, prefetch-pipelined)
//   phase A: score a rows vs s_b              (ldcs, 2-row interleave)
//   softmax over 1024 scores
//   broadcast write out (plain write-back stores -> L2-resident)
//
// a, b : [128, 1024, 300] fp32   out : [128, 1024, 300] fp32

#define BATCH   128
#define NROWS   1024
#define DIM     300
#define NF4     75
#define EPSV    1e-7f

__device__ __forceinline__ float dot4(float4 x, float4 y) {
    return x.x * y.x + x.y * y.y + x.z * y.z + x.w * y.w;
}
__device__ __forceinline__ void fma4(float4& a, float4 v, float s) {
    a.x += v.x * s; a.y += v.y * s; a.z += v.z * s; a.w += v.w * s;
}
__device__ __forceinline__ void add4(float4& a, float4 v) {
    a.x += v.x; a.y += v.y; a.z += v.z; a.w += v.w;
}

// ---------------------------------------------------------------------------
// grid = 128 (batch), block = 1024 (32 warps)
// ---------------------------------------------------------------------------
__global__ __launch_bounds__(1024, 1) void fused_all_kernel(
    const float* __restrict__ a, const float* __restrict__ b,
    float* __restrict__ out)
{
    const int batch = blockIdx.x;
    const int warp  = threadIdx.x >> 5;
    const int lane  = threadIdx.x & 31;

    __shared__ float4 sw4[32][NF4 + 1];   // 38.9 KB cross-warp partials
    __shared__ float4 ssh4[NF4];          // s_b
    __shared__ float  probs[NROWS];
    __shared__ float  red[32];

    const float4 z4 = make_float4(0.f, 0.f, 0.f, 0.f);

    // ---- phase B: s_b = sum of normalized b rows (prefetch-pipelined) ----
    {
        const float4* b4 = reinterpret_cast<const float4*>(b)
                         + (size_t)batch * NROWS * NF4;
        float4 acc0 = z4, acc1 = z4, acc2 = z4;

        // preload first row (r = warp)
        const float4* row0 = b4 + warp * NF4;
        float4 c0 = __ldcs(row0 + lane);
        float4 c1 = __ldcs(row0 + lane + 32);
        float4 c2 = (lane < NF4 - 64) ? __ldcs(row0 + lane + 64) : z4;

        for (int r = warp; r < NROWS; r += 32) {
            // issue next row's loads BEFORE this row's reduction chain
            float4 n0 = z4, n1 = z4, n2 = z4;
            if (r + 32 < NROWS) {
                const float4* nrow = b4 + (r + 32) * NF4;
                n0 = __ldcs(nrow + lane);
                n1 = __ldcs(nrow + lane + 32);
                if (lane < NF4 - 64) n2 = __ldcs(nrow + lane + 64);
            }

            float ss = dot4(c0, c0) + dot4(c1, c1) + dot4(c2, c2);
#pragma unroll
            for (int o = 16; o > 0; o >>= 1)
                ss += __shfl_xor_sync(0xffffffffu, ss, o);
            const float inv = rsqrtf(fmaxf(ss, EPSV));
            fma4(acc0, c0, inv);
            fma4(acc1, c1, inv);
            fma4(acc2, c2, inv);

            c0 = n0; c1 = n1; c2 = n2;
        }
        sw4[warp][lane]      = acc0;
        sw4[warp][lane + 32] = acc1;
        if (lane < NF4 - 64) sw4[warp][lane + 64] = acc2;
    }
    __syncthreads();

    // fold 32 warp-partials -> ssh4 (75 active threads, fixed order)
    if (threadIdx.x < NF4) {
        float4 t = sw4[0][threadIdx.x];
#pragma unroll
        for (int w = 1; w < 32; w++) add4(t, sw4[w][threadIdx.x]);
        ssh4[threadIdx.x] = t;
    }
    __syncthreads();

    // ---- phase A: scores of a rows (2-row interleave) --------------------
    {
        const float4 s0 = ssh4[lane];
        const float4 s1 = ssh4[lane + 32];
        const float4 s2 = (lane < NF4 - 64) ? ssh4[lane + 64] : z4;

        const float4* a4 = reinterpret_cast<const float4*>(a)
                         + (size_t)batch * NROWS * NF4;

#pragma unroll 2
        for (int i = 0; i < 16; i++) {
            const int rA = warp + 64 * i;
            const float4* rowA = a4 + rA * NF4;
            const float4* rowB = rowA + 32 * NF4;
            const float4 A0 = __ldcs(rowA + lane);
            const float4 A1 = __ldcs(rowA + lane + 32);
            const float4 B0 = __ldcs(rowB + lane);
            const float4 B1 = __ldcs(rowB + lane + 32);
            const float4 A2 = (lane < NF4 - 64) ? __ldcs(rowA + lane + 64) : z4;
            const float4 B2 = (lane < NF4 - 64) ? __ldcs(rowB + lane + 64) : z4;

            float dA = dot4(A0, s0) + dot4(A1, s1) + dot4(A2, s2);
            float nA = dot4(A0, A0) + dot4(A1, A1) + dot4(A2, A2);
            float dB = dot4(B0, s0) + dot4(B1, s1) + dot4(B2, s2);
            float nB = dot4(B0, B0) + dot4(B1, B1) + dot4(B2, B2);
#pragma unroll
            for (int o = 16; o > 0; o >>= 1) {
                dA += __shfl_xor_sync(0xffffffffu, dA, o);
                nA += __shfl_xor_sync(0xffffffffu, nA, o);
                dB += __shfl_xor_sync(0xffffffffu, dB, o);
                nB += __shfl_xor_sync(0xffffffffu, nB, o);
            }
            if (lane == 0) {
                probs[rA]      = dA * rsqrtf(fmaxf(nA, EPSV));
                probs[rA + 32] = dB * rsqrtf(fmaxf(nB, EPSV));
            }
        }
    }
    __syncthreads();

    // ---- softmax over 1024 scores (thread t owns element t) --------------
    const float x = probs[threadIdx.x];

    float m = x;
#pragma unroll
    for (int o = 16; o > 0; o >>= 1)
        m = fmaxf(m, __shfl_xor_sync(0xffffffffu, m, o));
    if (lane == 0) red[warp] = m;
    __syncthreads();
    if (warp == 0) {
        float t = red[lane];
#pragma unroll
        for (int o = 16; o > 0; o >>= 1)
            t = fmaxf(t, __shfl_xor_sync(0xffffffffu, t, o));
        if (lane == 0) red[0] = t;
    }
    __syncthreads();
    const float M = red[0];

    const float e = __expf(x - M);

    float sum = e;
#pragma unroll
    for (int o = 16; o > 0; o >>= 1)
        sum += __shfl_xor_sync(0xffffffffu, sum, o);
    __syncthreads();                  // red[] reuse barrier
    if (lane == 0) red[warp] = sum;
    __syncthreads();
    if (warp == 0) {
        float t = red[lane];
#pragma unroll
        for (int o = 16; o > 0; o >>= 1)
            t += __shfl_xor_sync(0xffffffffu, t, o);
        if (lane == 0) red[0] = t;
    }
    __syncthreads();

    probs[threadIdx.x] = e * __frcp_rn(red[0]);
    __syncthreads();

    // ---- broadcast write: warp-per-row, plain write-back stores ----------
    float4* o4 = reinterpret_cast<float4*>(out) + (size_t)batch * NROWS * NF4;
#pragma unroll 4
    for (int r = warp; r < NROWS; r += 32) {
        const float p = probs[r];
        const float4 pv = make_float4(p, p, p, p);
        float4* row = o4 + r * NF4;
        row[lane]      = pv;
        row[lane + 32] = pv;
        if (lane < NF4 - 64) row[lane + 64] = pv;
    }
}

// ---------------------------------------------------------------------------
extern "C" void kernel_launch(void* const* d_in, const int* in_sizes, int n_in,
                              void* d_out, int out_size)
{
    const float* a = (const float*)d_in[0];
    const float* b = (const float*)d_in[1];
    float* out = (float*)d_out;

    fused_all_kernel<<<BATCH, 1024>>>(a, b, out);
}